// round 2
// baseline (speedup 1.0000x reference)
#include <cuda_runtime.h>
#include <cuda_bf16.h>
#include <math.h>
#include <stdint.h>

#define D 64
#define MAXNP 20096          // 157 * 128 (padded row count)
#define NSPLIT 4
#define CAP 1024
#define MARGIN 4e-5f
#define LDA 72               // smem row stride in bf16 elems (144B, conflict-free)

// ---------------- device scratch (no allocation allowed) -------------------
__device__ float g_fbn[MAXNP * D];
__device__ float g_twn[MAXNP * D];
__device__ __nv_bfloat16 g_fbh[MAXNP * D];
__device__ __nv_bfloat16 g_fbl[MAXNP * D];
__device__ __nv_bfloat16 g_twh[MAXNP * D];
__device__ __nv_bfloat16 g_twl[MAXNP * D];
__device__ float g_b1[NSPLIT * MAXNP];
__device__ float g_b2[NSPLIT * MAXNP];
__device__ int   g_i1[NSPLIT * MAXNP];
__device__ int   g_idx[MAXNP];
__device__ int   g_flagCnt;
__device__ int   g_flagRows[CAP];

// ---------------- PTX helpers ----------------------------------------------
__device__ __forceinline__ uint32_t saddr(const void* p) {
    return (uint32_t)__cvta_generic_to_shared(p);
}
__device__ __forceinline__ void ldm_x4(uint32_t* r, uint32_t addr) {
    asm volatile("ldmatrix.sync.aligned.m8n8.x4.shared.b16 {%0,%1,%2,%3}, [%4];"
                 : "=r"(r[0]), "=r"(r[1]), "=r"(r[2]), "=r"(r[3]) : "r"(addr));
}
__device__ __forceinline__ void mma_bf16(float* d, const uint32_t* a,
                                         uint32_t b0, uint32_t b1) {
    asm volatile(
        "mma.sync.aligned.m16n8k16.row.col.f32.bf16.bf16.f32 "
        "{%0,%1,%2,%3}, {%4,%5,%6,%7}, {%8,%9}, {%0,%1,%2,%3};"
        : "+f"(d[0]), "+f"(d[1]), "+f"(d[2]), "+f"(d[3])
        : "r"(a[0]), "r"(a[1]), "r"(a[2]), "r"(a[3]), "r"(b0), "r"(b1));
}
#define CP16(dst, src) \
    asm volatile("cp.async.cg.shared.global [%0], [%1], 16;" :: "r"(dst), "l"(src))
#define CP_COMMIT() asm volatile("cp.async.commit_group;" ::)
#define CP_WAIT_ALL() asm volatile("cp.async.wait_group 0;" ::)

// ---------------------------------------------------------------------------
// Phase 1: normalize + bf16 hi/lo split (warp per row; rows >= n zero-padded)
// ---------------------------------------------------------------------------
__global__ void __launch_bounds__(256) normsplit_kernel(
    const float* __restrict__ in, float* __restrict__ nf,
    __nv_bfloat16* __restrict__ hi, __nv_bfloat16* __restrict__ lo, int n) {
    int w = threadIdx.x >> 5, lane = threadIdx.x & 31;
    int row = blockIdx.x * 8 + w;
    if (row >= MAXNP) return;
    if (row < n) {
        float2 v = reinterpret_cast<const float2*>(in + (size_t)row * D)[lane];
        float ss = v.x * v.x + v.y * v.y;
        #pragma unroll
        for (int off = 16; off; off >>= 1) ss += __shfl_xor_sync(0xffffffffu, ss, off);
        float scale = 1.0f / fmaxf(sqrtf(ss), 1e-8f);
        float a = v.x * scale, b = v.y * scale;
        reinterpret_cast<float2*>(nf + (size_t)row * D)[lane] = make_float2(a, b);
        __nv_bfloat16 ah = __float2bfloat16(a), bh = __float2bfloat16(b);
        __nv_bfloat16 al = __float2bfloat16(a - __bfloat162float(ah));
        __nv_bfloat16 bl = __float2bfloat16(b - __bfloat162float(bh));
        reinterpret_cast<__nv_bfloat162*>(hi + (size_t)row * D)[lane] =
            __nv_bfloat162(ah, bh);
        reinterpret_cast<__nv_bfloat162*>(lo + (size_t)row * D)[lane] =
            __nv_bfloat162(al, bl);
    } else {
        reinterpret_cast<float2*>(nf + (size_t)row * D)[lane] = make_float2(0.f, 0.f);
        __nv_bfloat162 z(__float2bfloat16(0.f), __float2bfloat16(0.f));
        reinterpret_cast<__nv_bfloat162*>(hi + (size_t)row * D)[lane] = z;
        reinterpret_cast<__nv_bfloat162*>(lo + (size_t)row * D)[lane] = z;
    }
}

__global__ void reset_kernel() { g_flagCnt = 0; }

// ---------------------------------------------------------------------------
// Phase 2: split-bf16 tensor-core GEMM + fused per-row top-2.
// 512 threads, BM=BN=128, K=64 resident. 4x4 warp grid, 32x32 warp tiles.
// acc += Ahi*Bhi + Ahi*Blo + Alo*Bhi  (error <= ~1.1e-5 on unit-norm rows)
// ---------------------------------------------------------------------------
__global__ void __launch_bounds__(512, 1) gemm_top2_kernel(int n_fb, int n_tw) {
    extern __shared__ __align__(16) __nv_bfloat16 sm[];
    __nv_bfloat16* Ah = sm;                       // 128*72
    __nv_bfloat16* Al = sm + 9216;
    __nv_bfloat16* BhBuf[2] = { sm + 2 * 9216, sm + 4 * 9216 };
    __nv_bfloat16* BlBuf[2] = { sm + 3 * 9216, sm + 5 * 9216 };

    const int tid = threadIdx.x;
    const int warp = tid >> 5, lane = tid & 31;
    const int wm = warp >> 2, wn = warp & 3;
    const int g = lane >> 2, tc = lane & 3;
    const int row0 = blockIdx.x * 128;
    const int split = blockIdx.y;

    // ---- load A (hi/lo) once ----
    {
        const uint2* sAh = (const uint2*)(g_fbh + (size_t)row0 * D);
        const uint2* sAl = (const uint2*)(g_fbl + (size_t)row0 * D);
        for (int i = tid; i < 2048; i += 512) {
            int r = i >> 4, c = i & 15;
            *(uint2*)&Ah[r * LDA + c * 4] = sAh[i];
            *(uint2*)&Al[r * LDA + c * 4] = sAl[i];
        }
    }

    const int nChunks = (n_tw + 127) >> 7;
    const int per = (nChunks + NSPLIT - 1) / NSPLIT;
    const int cBeg = split * per;
    const int cEnd = min(cBeg + per, nChunks);

    auto prefetch = [&](int ch, int b) {
        const char* srcH = (const char*)g_twh + (size_t)ch * 128 * 128;
        const char* srcL = (const char*)g_twl + (size_t)ch * 128 * 128;
        uint32_t dH = saddr(BhBuf[b]);
        uint32_t dL = saddr(BlBuf[b]);
        for (int i = tid; i < 1024; i += 512) {
            int r = i >> 3, c = i & 7;
            CP16(dH + r * 144 + c * 16, srcH + r * 128 + c * 16);
            CP16(dL + r * 144 + c * 16, srcL + r * 128 + c * 16);
        }
        CP_COMMIT();
    };

    float b1[4] = {-2.f, -2.f, -2.f, -2.f};
    float b2[4] = {-2.f, -2.f, -2.f, -2.f};
    int   i1[4] = {0, 0, 0, 0};

    int buf = 0;
    if (cBeg < cEnd) prefetch(cBeg, 0);

    for (int ch = cBeg; ch < cEnd; ch++) {
        CP_WAIT_ALL();
        __syncthreads();
        if (ch + 1 < cEnd) prefetch(ch + 1, buf ^ 1);
        const __nv_bfloat16* pBh = BhBuf[buf];
        const __nv_bfloat16* pBl = BlBuf[buf];
        const int col0 = ch << 7;

        float acc[2][4][4];
        #pragma unroll
        for (int i = 0; i < 2; i++)
            #pragma unroll
            for (int t = 0; t < 4; t++)
                #pragma unroll
                for (int q = 0; q < 4; q++) acc[i][t][q] = 0.f;

        #pragma unroll
        for (int ks = 0; ks < 4; ks++) {
            const int kc = ks * 16 + ((lane >> 4) << 3);
            const int rsel = lane & 15;
            uint32_t ah[2][4], al[2][4], bh[2][4], bl[2][4];
            #pragma unroll
            for (int i = 0; i < 2; i++) {
                int r = wm * 32 + i * 16 + rsel;
                ldm_x4(ah[i], saddr(&Ah[r * LDA + kc]));
                ldm_x4(al[i], saddr(&Al[r * LDA + kc]));
            }
            #pragma unroll
            for (int j = 0; j < 2; j++) {
                int r = wn * 32 + j * 16 + rsel;
                ldm_x4(bh[j], saddr(&pBh[r * LDA + kc]));
                ldm_x4(bl[j], saddr(&pBl[r * LDA + kc]));
            }
            #pragma unroll
            for (int i = 0; i < 2; i++)
                #pragma unroll
                for (int t = 0; t < 4; t++) {
                    int j = t >> 1, s = t & 1;
                    mma_bf16(acc[i][t], ah[i], bh[j][s], bh[j][s + 2]);
                    mma_bf16(acc[i][t], ah[i], bl[j][s], bl[j][s + 2]);
                    mma_bf16(acc[i][t], al[i], bh[j][s], bh[j][s + 2]);
                }
        }

        // fused top-2 epilogue for this chunk
        const bool full = (col0 + 128 <= n_tw);
        const int nb = col0 + wn * 32 + 2 * tc;
        #pragma unroll
        for (int i = 0; i < 2; i++)
            #pragma unroll
            for (int t = 0; t < 4; t++) {
                int n0 = nb + t * 8;
                #pragma unroll
                for (int q = 0; q < 4; q++) {
                    int lr = i * 2 + (q >> 1);
                    int n = n0 + (q & 1);
                    float v = acc[i][t][q];
                    if (full || n < n_tw) {
                        if (v > b1[lr]) { b2[lr] = b1[lr]; b1[lr] = v; i1[lr] = n; }
                        else if (v > b2[lr]) b2[lr] = v;
                    }
                }
            }
        buf ^= 1;
    }

    // ---- cross-lane (tc) merge ----
    #pragma unroll
    for (int lr = 0; lr < 4; lr++) {
        #pragma unroll
        for (int off = 1; off <= 2; off <<= 1) {
            float ob1 = __shfl_xor_sync(0xffffffffu, b1[lr], off);
            float ob2 = __shfl_xor_sync(0xffffffffu, b2[lr], off);
            int   oi1 = __shfl_xor_sync(0xffffffffu, i1[lr], off);
            if (ob1 > b1[lr] || (ob1 == b1[lr] && oi1 < i1[lr])) {
                b2[lr] = fmaxf(b1[lr], ob2); b1[lr] = ob1; i1[lr] = oi1;
            } else {
                b2[lr] = fmaxf(b2[lr], ob1);
            }
        }
    }

    // ---- cross-warp merge via smem (overlay on A region) ----
    __syncthreads();
    float* redB1 = (float*)sm;          // 128*4
    float* redB2 = redB1 + 512;
    int*   redI1 = (int*)(redB2 + 512);
    if (tc == 0) {
        #pragma unroll
        for (int lr = 0; lr < 4; lr++) {
            int row = wm * 32 + (lr >> 1) * 16 + g + (lr & 1) * 8;
            redB1[row * 4 + wn] = b1[lr];
            redB2[row * 4 + wn] = b2[lr];
            redI1[row * 4 + wn] = i1[lr];
        }
    }
    __syncthreads();
    if (tid < 128) {
        float B1 = -3.f, B2 = -3.f; int I1 = 0;
        #pragma unroll
        for (int w = 0; w < 4; w++) {
            float vb1 = redB1[tid * 4 + w], vb2 = redB2[tid * 4 + w];
            int vi1 = redI1[tid * 4 + w];
            if (vb1 > B1 || (vb1 == B1 && vi1 < I1)) {
                B2 = fmaxf(B1, vb2); B1 = vb1; I1 = vi1;
            } else {
                B2 = fmaxf(B2, vb1);
            }
        }
        size_t o = (size_t)split * MAXNP + row0 + tid;
        g_b1[o] = B1; g_b2[o] = B2; g_i1[o] = I1;
    }
}

// ---------------------------------------------------------------------------
// Phase 3: merge splits -> final idx + flag ambiguous rows
// ---------------------------------------------------------------------------
__global__ void __launch_bounds__(256) merge_kernel(int n_fb) {
    int row = blockIdx.x * 256 + threadIdx.x;
    if (row >= n_fb) return;
    float B1 = -3.f, B2 = -3.f; int I1 = 0;
    #pragma unroll
    for (int s = 0; s < NSPLIT; s++) {
        size_t o = (size_t)s * MAXNP + row;
        float vb1 = g_b1[o], vb2 = g_b2[o];
        int vi1 = g_i1[o];
        if (vb1 > B1 || (vb1 == B1 && vi1 < I1)) {
            B2 = fmaxf(B1, vb2); B1 = vb1; I1 = vi1;
        } else {
            B2 = fmaxf(B2, vb1);
        }
    }
    g_idx[row] = I1;
    if (B1 - B2 < MARGIN) {
        int p = atomicAdd(&g_flagCnt, 1);
        if (p < CAP) g_flagRows[p] = row;
    }
}

// ---------------------------------------------------------------------------
// Phase 4: exact fp32 rescan of flagged rows (block per flagged row)
// ---------------------------------------------------------------------------
__global__ void __launch_bounds__(256) fallback_kernel(int n_tw) {
    __shared__ float frow[D];
    __shared__ float sv[256];
    __shared__ int   si[256];
    int cnt = min(g_flagCnt, CAP);
    for (int f = blockIdx.x; f < cnt; f += gridDim.x) {
        int row = g_flagRows[f];
        if (threadIdx.x < D) frow[threadIdx.x] = g_fbn[(size_t)row * D + threadIdx.x];
        __syncthreads();
        float best = -3.f; int bi = 0;
        for (int c = threadIdx.x; c < n_tw; c += 256) {
            float s = 0.f;
            #pragma unroll
            for (int k = 0; k < D; k++) s = fmaf(frow[k], g_twn[(size_t)c * D + k], s);
            if (s > best) { best = s; bi = c; }
        }
        sv[threadIdx.x] = best; si[threadIdx.x] = bi;
        __syncthreads();
        for (int s = 128; s; s >>= 1) {
            if (threadIdx.x < s) {
                float v = sv[threadIdx.x + s]; int ix = si[threadIdx.x + s];
                if (v > sv[threadIdx.x] ||
                    (v == sv[threadIdx.x] && ix < si[threadIdx.x])) {
                    sv[threadIdx.x] = v; si[threadIdx.x] = ix;
                }
            }
            __syncthreads();
        }
        if (threadIdx.x == 0) g_idx[row] = si[0];
        __syncthreads();
    }
}

// ---------------------------------------------------------------------------
// Phase 5: head (attention MLP + softmax + weighted sum + output MLP + sigmoid)
// ---------------------------------------------------------------------------
__global__ void __launch_bounds__(256) head_kernel(
    const float* __restrict__ fb, const float* __restrict__ tw,
    const float* __restrict__ Wa1, const float* __restrict__ ba1,
    const float* __restrict__ Wa2, const float* __restrict__ ba2,
    const float* __restrict__ Wo1, const float* __restrict__ bo1,
    const float* __restrict__ Wo2, const float* __restrict__ bo2,
    float* __restrict__ out, int n_fb) {
    __shared__ float concat[8][128];
    __shared__ float wbuf[8][64];

    int w = threadIdx.x >> 5, lane = threadIdx.x & 31;
    int row = blockIdx.x * 8 + w;
    if (row >= n_fb) return;

    int bi = g_idx[row];

    float f0 = fb[(size_t)row * D + lane];
    float f1 = fb[(size_t)row * D + 32 + lane];
    float t0 = tw[(size_t)bi * D + lane];
    float t1 = tw[(size_t)bi * D + 32 + lane];
    concat[w][lane]      = f0;
    concat[w][32 + lane] = f1;
    concat[w][64 + lane] = t0;
    concat[w][96 + lane] = t1;
    __syncwarp();

    float h0 = ba1[lane], h1 = ba1[32 + lane];
    #pragma unroll 8
    for (int k = 0; k < 128; k++) {
        float cv = concat[w][k];
        h0 = fmaf(cv, Wa1[k * 64 + lane], h0);
        h1 = fmaf(cv, Wa1[k * 64 + 32 + lane], h1);
    }
    h0 = fmaxf(h0, 0.0f);
    h1 = fmaxf(h1, 0.0f);

    float p0 = h0 * Wa2[lane * 2 + 0] + h1 * Wa2[(32 + lane) * 2 + 0];
    float p1 = h0 * Wa2[lane * 2 + 1] + h1 * Wa2[(32 + lane) * 2 + 1];
    #pragma unroll
    for (int off = 16; off; off >>= 1) {
        p0 += __shfl_xor_sync(0xffffffffu, p0, off);
        p1 += __shfl_xor_sync(0xffffffffu, p1, off);
    }
    p0 += ba2[0]; p1 += ba2[1];
    float mx = fmaxf(p0, p1);
    float e0 = expf(p0 - mx), e1 = expf(p1 - mx);
    float inv = 1.0f / (e0 + e1);
    float a0 = e0 * inv, a1 = e1 * inv;

    wbuf[w][lane]      = a0 * f0 + a1 * t0;
    wbuf[w][32 + lane] = a0 * f1 + a1 * t1;
    __syncwarp();

    float gg = bo1[lane];
    #pragma unroll 8
    for (int d = 0; d < 64; d++)
        gg = fmaf(wbuf[w][d], Wo1[d * 32 + lane], gg);
    gg = fmaxf(gg, 0.0f);

    float o = gg * Wo2[lane];
    #pragma unroll
    for (int off = 16; off; off >>= 1) o += __shfl_xor_sync(0xffffffffu, o, off);

    if (lane == 0) out[row] = 1.0f / (1.0f + expf(-(o + bo2[0])));
}

// ---------------------------------------------------------------------------
extern "C" void kernel_launch(void* const* d_in, const int* in_sizes, int n_in,
                              void* d_out, int out_size) {
    const float* fb  = (const float*)d_in[0];
    const float* tw  = (const float*)d_in[1];
    const float* Wa1 = (const float*)d_in[2];
    const float* ba1 = (const float*)d_in[3];
    const float* Wa2 = (const float*)d_in[4];
    const float* ba2 = (const float*)d_in[5];
    const float* Wo1 = (const float*)d_in[6];
    const float* bo1 = (const float*)d_in[7];
    const float* Wo2 = (const float*)d_in[8];
    const float* bo2 = (const float*)d_in[9];
    float* out = (float*)d_out;

    int n_fb = in_sizes[0] / D;
    int n_tw = in_sizes[1] / D;

    float *fbn_p, *twn_p;
    __nv_bfloat16 *fbh_p, *fbl_p, *twh_p, *twl_p;
    cudaGetSymbolAddress((void**)&fbn_p, g_fbn);
    cudaGetSymbolAddress((void**)&twn_p, g_twn);
    cudaGetSymbolAddress((void**)&fbh_p, g_fbh);
    cudaGetSymbolAddress((void**)&fbl_p, g_fbl);
    cudaGetSymbolAddress((void**)&twh_p, g_twh);
    cudaGetSymbolAddress((void**)&twl_p, g_twl);

    const int SMEM_BYTES = 6 * 9216 * 2;   // 110592
    cudaFuncSetAttribute(gemm_top2_kernel,
                         cudaFuncAttributeMaxDynamicSharedMemorySize, SMEM_BYTES);

    normsplit_kernel<<<MAXNP / 8, 256>>>(fb, fbn_p, fbh_p, fbl_p, n_fb);
    normsplit_kernel<<<MAXNP / 8, 256>>>(tw, twn_p, twh_p, twl_p, n_tw);
    reset_kernel<<<1, 1>>>();

    dim3 grid((n_fb + 127) / 128, NSPLIT);
    gemm_top2_kernel<<<grid, 512, SMEM_BYTES>>>(n_fb, n_tw);

    merge_kernel<<<(n_fb + 255) / 256, 256>>>(n_fb);
    fallback_kernel<<<64, 256>>>(n_tw);

    head_kernel<<<(n_fb + 7) / 8, 256>>>(fb, tw, Wa1, ba1, Wa2, ba2,
                                         Wo1, bo1, Wo2, bo2, out, n_fb);
}

// round 4
// speedup vs baseline: 1.0809x; 1.0809x over previous
#include <cuda_runtime.h>
#include <cuda_bf16.h>
#include <math.h>
#include <stdint.h>

#define D 64
#define NPA 20096            // padded fb rows (157*128)
#define NPB 20224            // padded tw rows (158*128)
#define NRB 157              // fb row blocks
#define NTB 158              // tw tiles
#define NSPLIT 8
#define CAP 2048
#define MARGIN 4e-5f

// ---------------- device scratch ----------------
// Swizzled bf16 tiles: per 128-row block, 32KB = [hi 16KB | lo 16KB],
// row r = 128 bytes, 16B chunk c stored at position (c ^ (r&7)).
__device__ char g_fbS[NRB * 32768];
__device__ char g_twS[NTB * 32768];
__device__ float g_fbn[NPA * D];
__device__ float g_twn[NPB * D];
__device__ float g_b1[NSPLIT * NPA];
__device__ float g_b2[NSPLIT * NPA];
__device__ int   g_i1[NSPLIT * NPA];
__device__ int   g_idx[NPA];
__device__ int   g_flagCnt;
__device__ int   g_flagRows[CAP];

// ---------------- PTX helpers ----------------
__device__ __forceinline__ uint32_t saddr(const void* p) {
    return (uint32_t)__cvta_generic_to_shared(p);
}
__device__ __forceinline__ void ldm_x4(uint32_t* r, uint32_t addr) {
    asm volatile("ldmatrix.sync.aligned.m8n8.x4.shared.b16 {%0,%1,%2,%3}, [%4];"
                 : "=r"(r[0]), "=r"(r[1]), "=r"(r[2]), "=r"(r[3]) : "r"(addr));
}
__device__ __forceinline__ void mma_bf16(float* d, const uint32_t* a,
                                         uint32_t b0, uint32_t b1) {
    asm volatile(
        "mma.sync.aligned.m16n8k16.row.col.f32.bf16.bf16.f32 "
        "{%0,%1,%2,%3}, {%4,%5,%6,%7}, {%8,%9}, {%0,%1,%2,%3};"
        : "+f"(d[0]), "+f"(d[1]), "+f"(d[2]), "+f"(d[3])
        : "r"(a[0]), "r"(a[1]), "r"(a[2]), "r"(a[3]), "r"(b0), "r"(b1));
}

#define MBARRIER_INIT(a, cnt) \
    asm volatile("mbarrier.init.shared.b64 [%0], %1;" :: "r"(a), "r"(cnt) : "memory")
#define MBARRIER_INVAL(a) \
    asm volatile("mbarrier.inval.shared.b64 [%0];" :: "r"(a) : "memory")
#define EXPECT_TX(mbar, bytes) \
    asm volatile("mbarrier.arrive.expect_tx.shared.b64 _, [%0], %1;" \
                 :: "r"(mbar), "r"(bytes) : "memory")
#define BULK_G2S(dst, src, bytes, mbar) \
    asm volatile("cp.async.bulk.shared::cluster.global.mbarrier::complete_tx::bytes " \
                 "[%0], [%1], %2, [%3];" \
                 :: "r"(dst), "l"(src), "r"(bytes), "r"(mbar) : "memory")
#define FENCE_ASYNC() asm volatile("fence.proxy.async;" ::: "memory")

#define MBARRIER_WAIT_PARITY(mbar_smem_addr, phase_parity) do { \
    uint32_t _mbar = (uint32_t)(mbar_smem_addr); \
    uint32_t _parity = (uint32_t)(phase_parity); \
    uint32_t _done; \
    asm volatile( \
        "{\n\t.reg .pred p;\n\t" \
        "mbarrier.try_wait.parity.acquire.cta.shared::cta.b64 p, [%1], %2;\n\t" \
        "selp.b32 %0, 1, 0, p;\n\t}" \
        : "=r"(_done) : "r"(_mbar), "r"(_parity) : "memory"); \
    if (!_done) { \
        asm volatile( \
            "{\n\t.reg .pred P1;\n\t" \
            "WAIT_LOOP_%=:\n\t" \
            "mbarrier.try_wait.parity.acquire.cta.shared::cta.b64 P1, [%0], %1, 0x989680;\n\t" \
            "@P1 bra.uni WAIT_DONE_%=;\n\t" \
            "bra.uni WAIT_LOOP_%=;\n\t" \
            "WAIT_DONE_%=:\n\t}" \
            :: "r"(_mbar), "r"(_parity) : "memory"); \
    } \
} while (0)

// SMEM layout (relative to 1KB-aligned base)
#define MB_A  0
#define MB_B0 8
#define MB_B1 16
#define SA    1024                  // A: 32KB (hi 16KB | lo 16KB)
#define SB0   (SA + 32768)
#define SB1   (SB0 + 32768)
#define SMEM_ALLOC (SB1 + 32768 + 1024)   // + alignment slack

// ---------------------------------------------------------------------------
// Phase 1: normalize + hi/lo split into SWIZZLED tile layout (+ zero-pad).
// Warp per row; lane holds 2 elems (4 bytes of each bf16 row).
// ---------------------------------------------------------------------------
__device__ __forceinline__ void prep_row(const float* __restrict__ in, int n, int row,
                                         int lane, float* __restrict__ nf,
                                         char* __restrict__ sw) {
    int rr = row & 127;
    char* base = sw + (size_t)(row >> 7) * 32768;
    int chunk = (lane >> 2) ^ (rr & 7);
    int off = rr * 128 + (chunk << 4) + (lane & 3) * 4;
    if (row < n) {
        float2 v = reinterpret_cast<const float2*>(in + (size_t)row * D)[lane];
        float ss = v.x * v.x + v.y * v.y;
        #pragma unroll
        for (int o = 16; o; o >>= 1) ss += __shfl_xor_sync(0xffffffffu, ss, o);
        float scale = 1.0f / fmaxf(sqrtf(ss), 1e-8f);
        float a = v.x * scale, b = v.y * scale;
        reinterpret_cast<float2*>(nf + (size_t)row * D)[lane] = make_float2(a, b);
        __nv_bfloat16 ah = __float2bfloat16(a), bh = __float2bfloat16(b);
        __nv_bfloat16 al = __float2bfloat16(a - __bfloat162float(ah));
        __nv_bfloat16 bl = __float2bfloat16(b - __bfloat162float(bh));
        *(__nv_bfloat162*)(base + off)         = __nv_bfloat162(ah, bh);
        *(__nv_bfloat162*)(base + 16384 + off) = __nv_bfloat162(al, bl);
    } else {
        reinterpret_cast<float2*>(nf + (size_t)row * D)[lane] = make_float2(0.f, 0.f);
        __nv_bfloat162 z(__float2bfloat16(0.f), __float2bfloat16(0.f));
        *(__nv_bfloat162*)(base + off)         = z;
        *(__nv_bfloat162*)(base + 16384 + off) = z;
    }
}

__global__ void __launch_bounds__(256) prep_kernel(const float* __restrict__ fb,
                                                   const float* __restrict__ tw,
                                                   int n_fb, int n_tw) {
    if (blockIdx.x == 0 && threadIdx.x == 0) g_flagCnt = 0;
    int w = threadIdx.x >> 5, lane = threadIdx.x & 31;
    int row = blockIdx.x * 8 + w;
    if (row < NPA) prep_row(fb, n_fb, row, lane, g_fbn, g_fbS);
    if (row < NPB) prep_row(tw, n_tw, row, lane, g_twn, g_twS);
}

// ---------------------------------------------------------------------------
// Phase 2: mma.sync bf16 3-term GEMM + fused in-register top-2.
// 512 threads, BM=BN=128, K=64 resident. Tiles fed by cp.async.bulk (1D TMA)
// from pre-swizzled global scratch; double-buffered B with mbarriers.
// ---------------------------------------------------------------------------
__global__ void __launch_bounds__(512, 1) gemm_tc_kernel(int n_fb, int n_tw) {
    extern __shared__ __align__(128) char smraw[];
    uint32_t sb = (saddr(smraw) + 1023u) & ~1023u;
    char* sbase = smraw + (sb - saddr(smraw));

    const int tid = threadIdx.x;
    const int warp = tid >> 5, lane = tid & 31;
    const int wm = warp >> 2, wn = warp & 3;
    const int g = lane >> 2, tc = lane & 3;
    const int row0 = blockIdx.x * 128;
    const int split = blockIdx.y;

    const int nT = (n_tw + 127) >> 7;
    const int per = (nT + NSPLIT - 1) / NSPLIT;
    const int t0 = split * per;
    const int T = min(t0 + per, nT) - t0;

    if (tid == 0) {
        MBARRIER_INIT(sb + MB_A, 1);
        MBARRIER_INIT(sb + MB_B0, 1);
        MBARRIER_INIT(sb + MB_B1, 1);
    }
    __syncthreads();
    if (tid == 0) {
        FENCE_ASYNC();
        EXPECT_TX(sb + MB_A, 32768u);
        BULK_G2S(sb + SA, g_fbS + (size_t)blockIdx.x * 32768, 32768u, sb + MB_A);
        if (T > 0) {
            EXPECT_TX(sb + MB_B0, 32768u);
            BULK_G2S(sb + SB0, g_twS + (size_t)t0 * 32768, 32768u, sb + MB_B0);
        }
        if (T > 1) {
            EXPECT_TX(sb + MB_B1, 32768u);
            BULK_G2S(sb + SB1, g_twS + (size_t)(t0 + 1) * 32768, 32768u, sb + MB_B1);
        }
    }

    float b1 = -2.f, b2 = -2.f;
    int i1 = 0;
    int phB0 = 0, phB1 = 0;

    // ldmatrix base offsets (row-dependent part is loop-invariant)
    const int rA = wm * 32 + (lane & 15);        // A rows rA, rA+16
    const int rB = wn * 32 + (lane & 15);        // B rows rB, rB+16
    const int swA = rA & 7, swB = rB & 7;        // (r+16)&7 == r&7
    const uint32_t aBase = sb + SA + rA * 128;
    const int cHalf = (lane >> 4);               // 0 or 1: col-chunk half

    MBARRIER_WAIT_PARITY(sb + MB_A, 0);

    for (int i = 0; i < T; i++) {
        const int b = i & 1;
        const uint32_t SBx = sb + (b ? SB1 : SB0);
        const uint32_t mb = sb + (b ? MB_B1 : MB_B0);
        if (b == 0) { MBARRIER_WAIT_PARITY(mb, phB0); phB0 ^= 1; }
        else        { MBARRIER_WAIT_PARITY(mb, phB1); phB1 ^= 1; }

        const uint32_t bBase = SBx + rB * 128;

        float acc[2][4][4];
        #pragma unroll
        for (int x = 0; x < 2; x++)
            #pragma unroll
            for (int t = 0; t < 4; t++)
                #pragma unroll
                for (int q = 0; q < 4; q++) acc[x][t][q] = 0.f;

        #pragma unroll
        for (int ks = 0; ks < 4; ks++) {
            const int cc = ks * 2 + cHalf;
            const uint32_t aOff = (uint32_t)((cc ^ swA) << 4);
            const uint32_t bOff = (uint32_t)((cc ^ swB) << 4);
            uint32_t ah[2][4], al[2][4], bh[2][4], bl[2][4];
            #pragma unroll
            for (int x = 0; x < 2; x++) {
                ldm_x4(ah[x], aBase + x * 2048 + aOff);
                ldm_x4(al[x], aBase + x * 2048 + 16384 + aOff);
            }
            #pragma unroll
            for (int j = 0; j < 2; j++) {
                ldm_x4(bh[j], bBase + j * 2048 + bOff);
                ldm_x4(bl[j], bBase + j * 2048 + 16384 + bOff);
            }
            #pragma unroll
            for (int x = 0; x < 2; x++)
                #pragma unroll
                for (int t = 0; t < 4; t++) {
                    int j = t >> 1, s = t & 1;
                    mma_bf16(acc[x][t], ah[x], bh[j][s], bh[j][s + 2]);
                    mma_bf16(acc[x][t], ah[x], bl[j][s], bl[j][s + 2]);
                    mma_bf16(acc[x][t], al[x], bh[j][s], bh[j][s + 2]);
                }
        }

        // fused top-2 epilogue for this tile
        const int col0 = (t0 + i) << 7;
        const bool full = (col0 + 128 <= n_tw);
        const int nb = col0 + wn * 32 + 2 * tc;
        #pragma unroll
        for (int x = 0; x < 2; x++)
            #pragma unroll
            for (int t = 0; t < 4; t++) {
                int n0 = nb + t * 8;
                #pragma unroll
                for (int q = 0; q < 4; q++) {
                    int n = n0 + (q & 1);
                    float v = acc[x][t][q];
                    if (full || n < n_tw) {
                        // track per (x, q>>1) row pair via shared b1/b2? rows differ!
                        // NOTE: rows handled below via per-row arrays.
                    }
                }
            }
        // per-row top-2: 4 rows per thread -> use arrays
        {
            float* B1p; float* B2p; int* I1p;   // silence unused warnings path
            (void)B1p; (void)B2p; (void)I1p;
        }
        // --- real epilogue with per-row state ---
        // (rows: lr = x*2 + (q>>1); maintain 4 running slots)
        {
            static_assert(true, "");
        }
        #pragma unroll
        for (int x = 0; x < 2; x++)
            #pragma unroll
            for (int t = 0; t < 4; t++) {
                int n0 = nb + t * 8;
                #pragma unroll
                for (int q = 0; q < 4; q++) {
                    (void)n0; (void)q;
                }
            }
        // consolidated below (see topB arrays)
        __syncthreads();
        if (tid == 0 && i + 2 < T) {
            FENCE_ASYNC();
            EXPECT_TX(mb, 32768u);
            BULK_G2S(SBx, g_twS + (size_t)(t0 + i + 2) * 32768, 32768u, mb);
        }
        // stash acc-derived top2 into per-row registers:
        // done inline above is wrong; do it here properly:
        #pragma unroll
        for (int x = 0; x < 2; x++)
            #pragma unroll
            for (int t = 0; t < 4; t++) {
                int n0 = nb + t * 8;
                #pragma unroll
                for (int q = 0; q < 4; q++) {
                    (void)x; (void)t; (void)q; (void)n0;
                }
            }
        (void)full;
    }
    // NOTE: epilogue restructured: the loop above is replaced by topB logic
    // (see gemm_tc_kernel2 comment) -- actual implementation below.
    // To keep a single kernel, the per-row top-2 is tracked in the arrays
    // declared here and updated inside the main loop via the macro below.
    // (This placeholder block is unreachable logic-wise; real updates occur
    //  in-loop through topUpd.)
    // -- results written by the merge section that follows --

    // Since C++ forbids retroactive edits, the actual top-2 state lives in
    // b1x/b2x/i1x declared before the loop in the compiled version below.
    (void)b1; (void)b2; (void)i1; (void)g; (void)sbase;
}

// ===========================================================================
// The kernel above was getting unwieldy; the clean, actually-used version:
// ===========================================================================
__global__ void __launch_bounds__(512, 1) gemm_tc_kernel2(int n_fb, int n_tw) {
    extern __shared__ __align__(128) char smraw[];
    uint32_t sb = (saddr(smraw) + 1023u) & ~1023u;
    char* sbase = smraw + (sb - saddr(smraw));

    const int tid = threadIdx.x;
    const int warp = tid >> 5, lane = tid & 31;
    const int wm = warp >> 2, wn = warp & 3;
    const int g = lane >> 2, tc = lane & 3;
    const int row0 = blockIdx.x * 128;
    const int split = blockIdx.y;

    const int nT = (n_tw + 127) >> 7;
    const int per = (nT + NSPLIT - 1) / NSPLIT;
    const int t0 = split * per;
    const int T = min(t0 + per, nT) - t0;

    if (tid == 0) {
        MBARRIER_INIT(sb + MB_A, 1);
        MBARRIER_INIT(sb + MB_B0, 1);
        MBARRIER_INIT(sb + MB_B1, 1);
    }
    __syncthreads();
    if (tid == 0) {
        FENCE_ASYNC();
        EXPECT_TX(sb + MB_A, 32768u);
        BULK_G2S(sb + SA, g_fbS + (size_t)blockIdx.x * 32768, 32768u, sb + MB_A);
        if (T > 0) {
            EXPECT_TX(sb + MB_B0, 32768u);
            BULK_G2S(sb + SB0, g_twS + (size_t)t0 * 32768, 32768u, sb + MB_B0);
        }
        if (T > 1) {
            EXPECT_TX(sb + MB_B1, 32768u);
            BULK_G2S(sb + SB1, g_twS + (size_t)(t0 + 1) * 32768, 32768u, sb + MB_B1);
        }
    }

    float b1[4] = {-2.f, -2.f, -2.f, -2.f};
    float b2[4] = {-2.f, -2.f, -2.f, -2.f};
    int   i1[4] = {0, 0, 0, 0};
    int phB0 = 0, phB1 = 0;

    const int rA = wm * 32 + (lane & 15);
    const int rB = wn * 32 + (lane & 15);
    const int swA = rA & 7, swB = rB & 7;
    const uint32_t aBase = sb + SA + rA * 128;
    const int cHalf = (lane >> 4);

    MBARRIER_WAIT_PARITY(sb + MB_A, 0);

    for (int i = 0; i < T; i++) {
        const int b = i & 1;
        const uint32_t SBx = sb + (b ? SB1 : SB0);
        const uint32_t mb = sb + (b ? MB_B1 : MB_B0);
        if (b == 0) { MBARRIER_WAIT_PARITY(mb, phB0); phB0 ^= 1; }
        else        { MBARRIER_WAIT_PARITY(mb, phB1); phB1 ^= 1; }

        const uint32_t bBase = SBx + rB * 128;

        float acc[2][4][4];
        #pragma unroll
        for (int x = 0; x < 2; x++)
            #pragma unroll
            for (int t = 0; t < 4; t++)
                #pragma unroll
                for (int q = 0; q < 4; q++) acc[x][t][q] = 0.f;

        #pragma unroll
        for (int ks = 0; ks < 4; ks++) {
            const int cc = ks * 2 + cHalf;
            const uint32_t aOff = (uint32_t)((cc ^ swA) << 4);
            const uint32_t bOff = (uint32_t)((cc ^ swB) << 4);
            uint32_t ah[2][4], al[2][4], bh[2][4], bl[2][4];
            #pragma unroll
            for (int x = 0; x < 2; x++) {
                ldm_x4(ah[x], aBase + x * 2048 + aOff);
                ldm_x4(al[x], aBase + x * 2048 + 16384 + aOff);
            }
            #pragma unroll
            for (int j = 0; j < 2; j++) {
                ldm_x4(bh[j], bBase + j * 2048 + bOff);
                ldm_x4(bl[j], bBase + j * 2048 + 16384 + bOff);
            }
            #pragma unroll
            for (int x = 0; x < 2; x++)
                #pragma unroll
                for (int t = 0; t < 4; t++) {
                    int j = t >> 1, s = t & 1;
                    mma_bf16(acc[x][t], ah[x], bh[j][s], bh[j][s + 2]);
                    mma_bf16(acc[x][t], ah[x], bl[j][s], bl[j][s + 2]);
                    mma_bf16(acc[x][t], al[x], bh[j][s], bh[j][s + 2]);
                }
        }

        const int col0 = (t0 + i) << 7;
        const bool full = (col0 + 128 <= n_tw);
        const int nb = col0 + wn * 32 + 2 * tc;
        #pragma unroll
        for (int x = 0; x < 2; x++)
            #pragma unroll
            for (int t = 0; t < 4; t++) {
                int n0 = nb + t * 8;
                #pragma unroll
                for (int q = 0; q < 4; q++) {
                    int lr = x * 2 + (q >> 1);
                    int n = n0 + (q & 1);
                    float v = acc[x][t][q];
                    if (full || n < n_tw) {
                        if (v > b1[lr]) { b2[lr] = b1[lr]; b1[lr] = v; i1[lr] = n; }
                        else if (v > b2[lr]) b2[lr] = v;
                    }
                }
            }

        __syncthreads();
        if (tid == 0 && i + 2 < T) {
            FENCE_ASYNC();
            EXPECT_TX(mb, 32768u);
            BULK_G2S(SBx, g_twS + (size_t)(t0 + i + 2) * 32768, 32768u, mb);
        }
    }

    // cross-lane (tc) merge
    #pragma unroll
    for (int lr = 0; lr < 4; lr++) {
        #pragma unroll
        for (int off = 1; off <= 2; off <<= 1) {
            float ob1 = __shfl_xor_sync(0xffffffffu, b1[lr], off);
            float ob2 = __shfl_xor_sync(0xffffffffu, b2[lr], off);
            int   oi1 = __shfl_xor_sync(0xffffffffu, i1[lr], off);
            if (ob1 > b1[lr] || (ob1 == b1[lr] && oi1 < i1[lr])) {
                b2[lr] = fmaxf(b1[lr], ob2); b1[lr] = ob1; i1[lr] = oi1;
            } else {
                b2[lr] = fmaxf(b2[lr], ob1);
            }
        }
    }

    // cross-warp merge via smem (overlay on A region; all reads of A done)
    __syncthreads();
    float* redB1 = (float*)(sbase + SA);         // 128*4 floats
    float* redB2 = redB1 + 512;
    int*   redI1 = (int*)(redB2 + 512);
    if (tc == 0) {
        #pragma unroll
        for (int lr = 0; lr < 4; lr++) {
            int row = wm * 32 + (lr >> 1) * 16 + g + (lr & 1) * 8;
            redB1[row * 4 + wn] = b1[lr];
            redB2[row * 4 + wn] = b2[lr];
            redI1[row * 4 + wn] = i1[lr];
        }
    }
    __syncthreads();
    if (tid < 128) {
        float B1 = -3.f, B2 = -3.f; int I1 = 0;
        #pragma unroll
        for (int w = 0; w < 4; w++) {
            float vb1 = redB1[tid * 4 + w], vb2 = redB2[tid * 4 + w];
            int vi1 = redI1[tid * 4 + w];
            if (vb1 > B1 || (vb1 == B1 && vi1 < I1)) {
                B2 = fmaxf(B1, vb2); B1 = vb1; I1 = vi1;
            } else {
                B2 = fmaxf(B2, vb1);
            }
        }
        size_t o = (size_t)split * NPA + row0 + tid;
        g_b1[o] = B1; g_b2[o] = B2; g_i1[o] = I1;
    }
    __syncthreads();
    if (tid == 0) {
        MBARRIER_INVAL(sb + MB_A);
        MBARRIER_INVAL(sb + MB_B0);
        MBARRIER_INVAL(sb + MB_B1);
    }
}

// ---------------------------------------------------------------------------
// Phase 3: merge splits -> final idx + flag ambiguous rows
// ---------------------------------------------------------------------------
__global__ void __launch_bounds__(256) merge_kernel(int n_fb) {
    int row = blockIdx.x * 256 + threadIdx.x;
    if (row >= n_fb) return;
    float B1 = -3.f, B2 = -3.f; int I1 = 0;
    #pragma unroll
    for (int s = 0; s < NSPLIT; s++) {
        size_t o = (size_t)s * NPA + row;
        float vb1 = g_b1[o], vb2 = g_b2[o];
        int vi1 = g_i1[o];
        if (vb1 > B1 || (vb1 == B1 && vi1 < I1)) {
            B2 = fmaxf(B1, vb2); B1 = vb1; I1 = vi1;
        } else {
            B2 = fmaxf(B2, vb1);
        }
    }
    g_idx[row] = I1;
    if (B1 - B2 < MARGIN) {
        int p = atomicAdd(&g_flagCnt, 1);
        if (p < CAP) g_flagRows[p] = row;
    }
}

// ---------------------------------------------------------------------------
// Phase 4: exact fp32 rescan of flagged rows
// ---------------------------------------------------------------------------
__global__ void __launch_bounds__(256) fallback_kernel(int n_tw) {
    __shared__ float frow[D];
    __shared__ float sv[256];
    __shared__ int   si[256];
    int cnt = min(g_flagCnt, CAP);
    for (int f = blockIdx.x; f < cnt; f += gridDim.x) {
        int row = g_flagRows[f];
        if (threadIdx.x < D) frow[threadIdx.x] = g_fbn[(size_t)row * D + threadIdx.x];
        __syncthreads();
        float best = -3.f; int bi = 0;
        for (int c = threadIdx.x; c < n_tw; c += 256) {
            float s = 0.f;
            #pragma unroll
            for (int k = 0; k < D; k++) s = fmaf(frow[k], g_twn[(size_t)c * D + k], s);
            if (s > best) { best = s; bi = c; }
        }
        sv[threadIdx.x] = best; si[threadIdx.x] = bi;
        __syncthreads();
        for (int s = 128; s; s >>= 1) {
            if (threadIdx.x < s) {
                float v = sv[threadIdx.x + s]; int ix = si[threadIdx.x + s];
                if (v > sv[threadIdx.x] ||
                    (v == sv[threadIdx.x] && ix < si[threadIdx.x])) {
                    sv[threadIdx.x] = v; si[threadIdx.x] = ix;
                }
            }
            __syncthreads();
        }
        if (threadIdx.x == 0) g_idx[row] = si[0];
        __syncthreads();
    }
}

// ---------------------------------------------------------------------------
// Phase 5: head MLPs
// ---------------------------------------------------------------------------
__global__ void __launch_bounds__(256) head_kernel(
    const float* __restrict__ fb, const float* __restrict__ tw,
    const float* __restrict__ Wa1, const float* __restrict__ ba1,
    const float* __restrict__ Wa2, const float* __restrict__ ba2,
    const float* __restrict__ Wo1, const float* __restrict__ bo1,
    const float* __restrict__ Wo2, const float* __restrict__ bo2,
    float* __restrict__ out, int n_fb) {
    __shared__ float concat[8][128];
    __shared__ float wbuf[8][64];

    int w = threadIdx.x >> 5, lane = threadIdx.x & 31;
    int row = blockIdx.x * 8 + w;
    if (row >= n_fb) return;

    int bi = g_idx[row];

    float f0 = fb[(size_t)row * D + lane];
    float f1 = fb[(size_t)row * D + 32 + lane];
    float t0 = tw[(size_t)bi * D + lane];
    float t1 = tw[(size_t)bi * D + 32 + lane];
    concat[w][lane]      = f0;
    concat[w][32 + lane] = f1;
    concat[w][64 + lane] = t0;
    concat[w][96 + lane] = t1;
    __syncwarp();

    float h0 = ba1[lane], h1 = ba1[32 + lane];
    #pragma unroll 8
    for (int k = 0; k < 128; k++) {
        float cv = concat[w][k];
        h0 = fmaf(cv, Wa1[k * 64 + lane], h0);
        h1 = fmaf(cv, Wa1[k * 64 + 32 + lane], h1);
    }
    h0 = fmaxf(h0, 0.0f);
    h1 = fmaxf(h1, 0.0f);

    float p0 = h0 * Wa2[lane * 2 + 0] + h1 * Wa2[(32 + lane) * 2 + 0];
    float p1 = h0 * Wa2[lane * 2 + 1] + h1 * Wa2[(32 + lane) * 2 + 1];
    #pragma unroll
    for (int off = 16; off; off >>= 1) {
        p0 += __shfl_xor_sync(0xffffffffu, p0, off);
        p1 += __shfl_xor_sync(0xffffffffu, p1, off);
    }
    p0 += ba2[0]; p1 += ba2[1];
    float mx = fmaxf(p0, p1);
    float e0 = expf(p0 - mx), e1 = expf(p1 - mx);
    float inv = 1.0f / (e0 + e1);
    float a0 = e0 * inv, a1 = e1 * inv;

    wbuf[w][lane]      = a0 * f0 + a1 * t0;
    wbuf[w][32 + lane] = a0 * f1 + a1 * t1;
    __syncwarp();

    float gg = bo1[lane];
    #pragma unroll 8
    for (int d = 0; d < 64; d++)
        gg = fmaf(wbuf[w][d], Wo1[d * 32 + lane], gg);
    gg = fmaxf(gg, 0.0f);

    float o = gg * Wo2[lane];
    #pragma unroll
    for (int off = 16; off; off >>= 1) o += __shfl_xor_sync(0xffffffffu, o, off);

    if (lane == 0) out[row] = 1.0f / (1.0f + expf(-(o + bo2[0])));
}

// ---------------------------------------------------------------------------
extern "C" void kernel_launch(void* const* d_in, const int* in_sizes, int n_in,
                              void* d_out, int out_size) {
    const float* fb  = (const float*)d_in[0];
    const float* tw  = (const float*)d_in[1];
    const float* Wa1 = (const float*)d_in[2];
    const float* ba1 = (const float*)d_in[3];
    const float* Wa2 = (const float*)d_in[4];
    const float* ba2 = (const float*)d_in[5];
    const float* Wo1 = (const float*)d_in[6];
    const float* bo1 = (const float*)d_in[7];
    const float* Wo2 = (const float*)d_in[8];
    const float* bo2 = (const float*)d_in[9];
    float* out = (float*)d_out;

    int n_fb = in_sizes[0] / D;
    int n_tw = in_sizes[1] / D;

    static int smem_set = 0;
    if (!smem_set) {
        cudaFuncSetAttribute(gemm_tc_kernel2,
                             cudaFuncAttributeMaxDynamicSharedMemorySize, SMEM_ALLOC);
        smem_set = 1;
    }

    prep_kernel<<<NPB / 8, 256>>>(fb, tw, n_fb, n_tw);

    dim3 grid((n_fb + 127) / 128, NSPLIT);
    gemm_tc_kernel2<<<grid, 512, SMEM_ALLOC>>>(n_fb, n_tw);

    merge_kernel<<<(n_fb + 255) / 256, 256>>>(n_fb);
    fallback_kernel<<<64, 256>>>(n_tw);

    head_kernel<<<(n_fb + 7) / 8, 256>>>(fb, tw, Wa1, ba1, Wa2, ba2,
                                         Wo1, bo1, Wo2, bo2, out, n_fb);
}

// round 5
// speedup vs baseline: 1.9482x; 1.8024x over previous
#include <cuda_runtime.h>
#include <cuda_bf16.h>
#include <math.h>
#include <stdint.h>

#define D 64
#define NPA 20096            // padded fb rows (157*128)
#define NPB 20224            // padded tw rows (158*128)
#define NRB 157              // fb row blocks
#define NTB 158              // tw tiles
#define NSPLIT 8
#define CAP 2048
#define MARGIN 2e-5f

// ---------------- device scratch ----------------
// Swizzled bf16 tiles: per 128-row block, 32KB = [hi 16KB | lo 16KB],
// row r = 128 bytes, 16B chunk c stored at position (c ^ (r&7)).
__device__ char g_fbS[NRB * 32768];
__device__ char g_twS[NTB * 32768];
__device__ float g_fbn[NPA * D];
__device__ float g_twn[NPB * D];
__device__ float g_b1[NSPLIT * NPA];
__device__ float g_b2[NSPLIT * NPA];
__device__ int   g_i1[NSPLIT * NPA];
__device__ int   g_idx[NPA];
__device__ int   g_flagCnt;
__device__ int   g_flagRows[CAP];
__device__ float g_pb1[CAP * 8];
__device__ int   g_pi1[CAP * 8];

// ---------------- PTX helpers ----------------
__device__ __forceinline__ uint32_t saddr(const void* p) {
    return (uint32_t)__cvta_generic_to_shared(p);
}
__device__ __forceinline__ void ldm_x4(uint32_t* r, uint32_t addr) {
    asm volatile("ldmatrix.sync.aligned.m8n8.x4.shared.b16 {%0,%1,%2,%3}, [%4];"
                 : "=r"(r[0]), "=r"(r[1]), "=r"(r[2]), "=r"(r[3]) : "r"(addr));
}
__device__ __forceinline__ void mma_bf16(float* d, const uint32_t* a,
                                         uint32_t b0, uint32_t b1) {
    asm volatile(
        "mma.sync.aligned.m16n8k16.row.col.f32.bf16.bf16.f32 "
        "{%0,%1,%2,%3}, {%4,%5,%6,%7}, {%8,%9}, {%0,%1,%2,%3};"
        : "+f"(d[0]), "+f"(d[1]), "+f"(d[2]), "+f"(d[3])
        : "r"(a[0]), "r"(a[1]), "r"(a[2]), "r"(a[3]), "r"(b0), "r"(b1));
}

#define MBARRIER_INIT(a, cnt) \
    asm volatile("mbarrier.init.shared.b64 [%0], %1;" :: "r"(a), "r"(cnt) : "memory")
#define MBARRIER_INVAL(a) \
    asm volatile("mbarrier.inval.shared.b64 [%0];" :: "r"(a) : "memory")
#define EXPECT_TX(mbar, bytes) \
    asm volatile("mbarrier.arrive.expect_tx.shared.b64 _, [%0], %1;" \
                 :: "r"(mbar), "r"(bytes) : "memory")
#define BULK_G2S(dst, src, bytes, mbar) \
    asm volatile("cp.async.bulk.shared::cluster.global.mbarrier::complete_tx::bytes " \
                 "[%0], [%1], %2, [%3];" \
                 :: "r"(dst), "l"(src), "r"(bytes), "r"(mbar) : "memory")
#define FENCE_ASYNC() asm volatile("fence.proxy.async;" ::: "memory")

#define MBARRIER_WAIT_PARITY(mbar_smem_addr, phase_parity) do { \
    uint32_t _mbar = (uint32_t)(mbar_smem_addr); \
    uint32_t _parity = (uint32_t)(phase_parity); \
    uint32_t _done; \
    asm volatile( \
        "{\n\t.reg .pred p;\n\t" \
        "mbarrier.try_wait.parity.acquire.cta.shared::cta.b64 p, [%1], %2;\n\t" \
        "selp.b32 %0, 1, 0, p;\n\t}" \
        : "=r"(_done) : "r"(_mbar), "r"(_parity) : "memory"); \
    if (!_done) { \
        asm volatile( \
            "{\n\t.reg .pred P1;\n\t" \
            "WAIT_LOOP_%=:\n\t" \
            "mbarrier.try_wait.parity.acquire.cta.shared::cta.b64 P1, [%0], %1, 0x989680;\n\t" \
            "@P1 bra.uni WAIT_DONE_%=;\n\t" \
            "bra.uni WAIT_LOOP_%=;\n\t" \
            "WAIT_DONE_%=:\n\t}" \
            :: "r"(_mbar), "r"(_parity) : "memory"); \
    } \
} while (0)

// SMEM layout (relative to 1KB-aligned base)
#define MB_A  0
#define MB_B0 8
#define MB_B1 16
#define SA    1024                  // A: 32KB (hi 16KB | lo 16KB)
#define SB0   (SA + 32768)
#define SB1   (SB0 + 32768)
#define SMEM_ALLOC (SB1 + 32768 + 1024)

// ---------------------------------------------------------------------------
// Phase 1: normalize + hi/lo split into SWIZZLED tile layout (+ zero-pad).
// ---------------------------------------------------------------------------
__device__ __forceinline__ void prep_row(const float* __restrict__ in, int n, int row,
                                         int lane, float* __restrict__ nf,
                                         char* __restrict__ sw) {
    int rr = row & 127;
    char* base = sw + (size_t)(row >> 7) * 32768;
    int chunk = (lane >> 2) ^ (rr & 7);
    int off = rr * 128 + (chunk << 4) + (lane & 3) * 4;
    if (row < n) {
        float2 v = reinterpret_cast<const float2*>(in + (size_t)row * D)[lane];
        float ss = v.x * v.x + v.y * v.y;
        #pragma unroll
        for (int o = 16; o; o >>= 1) ss += __shfl_xor_sync(0xffffffffu, ss, o);
        float scale = 1.0f / fmaxf(sqrtf(ss), 1e-8f);
        float a = v.x * scale, b = v.y * scale;
        reinterpret_cast<float2*>(nf + (size_t)row * D)[lane] = make_float2(a, b);
        __nv_bfloat16 ah = __float2bfloat16(a), bh = __float2bfloat16(b);
        __nv_bfloat16 al = __float2bfloat16(a - __bfloat162float(ah));
        __nv_bfloat16 bl = __float2bfloat16(b - __bfloat162float(bh));
        *(__nv_bfloat162*)(base + off)         = __nv_bfloat162(ah, bh);
        *(__nv_bfloat162*)(base + 16384 + off) = __nv_bfloat162(al, bl);
    } else {
        reinterpret_cast<float2*>(nf + (size_t)row * D)[lane] = make_float2(0.f, 0.f);
        __nv_bfloat162 z(__float2bfloat16(0.f), __float2bfloat16(0.f));
        *(__nv_bfloat162*)(base + off)         = z;
        *(__nv_bfloat162*)(base + 16384 + off) = z;
    }
}

__global__ void __launch_bounds__(256) prep_kernel(const float* __restrict__ fb,
                                                   const float* __restrict__ tw,
                                                   int n_fb, int n_tw) {
    if (blockIdx.x == 0 && threadIdx.x == 0) g_flagCnt = 0;
    int w = threadIdx.x >> 5, lane = threadIdx.x & 31;
    int row = blockIdx.x * 8 + w;
    if (row < NPA) prep_row(fb, n_fb, row, lane, g_fbn, g_fbS);
    if (row < NPB) prep_row(tw, n_tw, row, lane, g_twn, g_twS);
}

// ---------------------------------------------------------------------------
// Phase 2: mma.sync bf16 3-term GEMM + fused in-register top-2.
// 512 threads, BM=BN=128, K=64 resident. Tiles fed by cp.async.bulk from
// pre-swizzled global scratch; double-buffered B with mbarriers.
// ---------------------------------------------------------------------------
__global__ void __launch_bounds__(512, 1) gemm_tc_kernel(int n_fb, int n_tw) {
    extern __shared__ __align__(128) char smraw[];
    uint32_t sb = (saddr(smraw) + 1023u) & ~1023u;
    char* sbase = smraw + (sb - saddr(smraw));

    const int tid = threadIdx.x;
    const int warp = tid >> 5, lane = tid & 31;
    const int wm = warp >> 2, wn = warp & 3;
    const int g = lane >> 2, tc = lane & 3;
    const int row0 = blockIdx.x * 128;
    const int split = blockIdx.y;

    const int nT = (n_tw + 127) >> 7;
    const int per = (nT + NSPLIT - 1) / NSPLIT;
    const int t0 = split * per;
    const int T = min(t0 + per, nT) - t0;

    if (tid == 0) {
        MBARRIER_INIT(sb + MB_A, 1);
        MBARRIER_INIT(sb + MB_B0, 1);
        MBARRIER_INIT(sb + MB_B1, 1);
    }
    __syncthreads();
    if (tid == 0) {
        FENCE_ASYNC();
        EXPECT_TX(sb + MB_A, 32768u);
        BULK_G2S(sb + SA, g_fbS + (size_t)blockIdx.x * 32768, 32768u, sb + MB_A);
        if (T > 0) {
            EXPECT_TX(sb + MB_B0, 32768u);
            BULK_G2S(sb + SB0, g_twS + (size_t)t0 * 32768, 32768u, sb + MB_B0);
        }
        if (T > 1) {
            EXPECT_TX(sb + MB_B1, 32768u);
            BULK_G2S(sb + SB1, g_twS + (size_t)(t0 + 1) * 32768, 32768u, sb + MB_B1);
        }
    }

    float b1[4] = {-2.f, -2.f, -2.f, -2.f};
    float b2[4] = {-2.f, -2.f, -2.f, -2.f};
    int   i1[4] = {0, 0, 0, 0};
    int phB0 = 0, phB1 = 0;

    const int rA = wm * 32 + (lane & 15);
    const int rB = wn * 32 + (lane & 15);
    const int swA = rA & 7, swB = rB & 7;
    const uint32_t aBase = sb + SA + rA * 128;
    const int cHalf = (lane >> 4);

    MBARRIER_WAIT_PARITY(sb + MB_A, 0);

    for (int i = 0; i < T; i++) {
        const int b = i & 1;
        const uint32_t SBx = sb + (b ? SB1 : SB0);
        const uint32_t mb = sb + (b ? MB_B1 : MB_B0);
        if (b == 0) { MBARRIER_WAIT_PARITY(mb, phB0); phB0 ^= 1; }
        else        { MBARRIER_WAIT_PARITY(mb, phB1); phB1 ^= 1; }

        const uint32_t bBase = SBx + rB * 128;

        float acc[2][4][4];
        #pragma unroll
        for (int x = 0; x < 2; x++)
            #pragma unroll
            for (int t = 0; t < 4; t++)
                #pragma unroll
                for (int q = 0; q < 4; q++) acc[x][t][q] = 0.f;

        #pragma unroll
        for (int ks = 0; ks < 4; ks++) {
            const int cc = ks * 2 + cHalf;
            const uint32_t aOff = (uint32_t)((cc ^ swA) << 4);
            const uint32_t bOff = (uint32_t)((cc ^ swB) << 4);
            uint32_t ah[2][4], al[2][4], bh[2][4], bl[2][4];
            #pragma unroll
            for (int x = 0; x < 2; x++) {
                ldm_x4(ah[x], aBase + x * 2048 + aOff);
                ldm_x4(al[x], aBase + x * 2048 + 16384 + aOff);
            }
            #pragma unroll
            for (int j = 0; j < 2; j++) {
                ldm_x4(bh[j], bBase + j * 2048 + bOff);
                ldm_x4(bl[j], bBase + j * 2048 + 16384 + bOff);
            }
            #pragma unroll
            for (int x = 0; x < 2; x++)
                #pragma unroll
                for (int t = 0; t < 4; t++) {
                    int j = t >> 1, s = t & 1;
                    mma_bf16(acc[x][t], ah[x], bh[j][s], bh[j][s + 2]);
                    mma_bf16(acc[x][t], ah[x], bl[j][s], bl[j][s + 2]);
                    mma_bf16(acc[x][t], al[x], bh[j][s], bh[j][s + 2]);
                }
        }

        // all smem reads of this tile done -> let DMA refill buffer while the
        // epilogue (register-only) runs
        __syncthreads();
        if (tid == 0 && i + 2 < T) {
            FENCE_ASYNC();
            EXPECT_TX(mb, 32768u);
            BULK_G2S(SBx, g_twS + (size_t)(t0 + i + 2) * 32768, 32768u, mb);
        }

        const int col0 = (t0 + i) << 7;
        const bool full = (col0 + 128 <= n_tw);
        const int nb = col0 + wn * 32 + 2 * tc;
        #pragma unroll
        for (int x = 0; x < 2; x++)
            #pragma unroll
            for (int t = 0; t < 4; t++) {
                int n0 = nb + t * 8;
                #pragma unroll
                for (int q = 0; q < 4; q++) {
                    int lr = x * 2 + (q >> 1);
                    int n = n0 + (q & 1);
                    float v = acc[x][t][q];
                    if (full || n < n_tw) {
                        if (v > b1[lr]) { b2[lr] = b1[lr]; b1[lr] = v; i1[lr] = n; }
                        else if (v > b2[lr]) b2[lr] = v;
                    }
                }
            }
    }

    // cross-lane (tc) merge
    #pragma unroll
    for (int lr = 0; lr < 4; lr++) {
        #pragma unroll
        for (int off = 1; off <= 2; off <<= 1) {
            float ob1 = __shfl_xor_sync(0xffffffffu, b1[lr], off);
            float ob2 = __shfl_xor_sync(0xffffffffu, b2[lr], off);
            int   oi1 = __shfl_xor_sync(0xffffffffu, i1[lr], off);
            if (ob1 > b1[lr] || (ob1 == b1[lr] && oi1 < i1[lr])) {
                b2[lr] = fmaxf(b1[lr], ob2); b1[lr] = ob1; i1[lr] = oi1;
            } else {
                b2[lr] = fmaxf(b2[lr], ob1);
            }
        }
    }

    // cross-warp merge via smem (overlay on A region; all reads of A done)
    __syncthreads();
    float* redB1 = (float*)(sbase + SA);
    float* redB2 = redB1 + 512;
    int*   redI1 = (int*)(redB2 + 512);
    if (tc == 0) {
        #pragma unroll
        for (int lr = 0; lr < 4; lr++) {
            int row = wm * 32 + (lr >> 1) * 16 + g + (lr & 1) * 8;
            redB1[row * 4 + wn] = b1[lr];
            redB2[row * 4 + wn] = b2[lr];
            redI1[row * 4 + wn] = i1[lr];
        }
    }
    __syncthreads();
    if (tid < 128) {
        float B1 = -3.f, B2 = -3.f; int I1 = 0;
        #pragma unroll
        for (int w = 0; w < 4; w++) {
            float vb1 = redB1[tid * 4 + w], vb2 = redB2[tid * 4 + w];
            int vi1 = redI1[tid * 4 + w];
            if (vb1 > B1 || (vb1 == B1 && vi1 < I1)) {
                B2 = fmaxf(B1, vb2); B1 = vb1; I1 = vi1;
            } else {
                B2 = fmaxf(B2, vb1);
            }
        }
        size_t o = (size_t)split * NPA + row0 + tid;
        g_b1[o] = B1; g_b2[o] = B2; g_i1[o] = I1;
    }
    __syncthreads();
    if (tid == 0) {
        MBARRIER_INVAL(sb + MB_A);
        MBARRIER_INVAL(sb + MB_B0);
        MBARRIER_INVAL(sb + MB_B1);
    }
}

// ---------------------------------------------------------------------------
// Phase 3: merge splits -> final idx + flag ambiguous rows
// ---------------------------------------------------------------------------
__global__ void __launch_bounds__(256) merge_kernel(int n_fb) {
    int row = blockIdx.x * 256 + threadIdx.x;
    if (row >= n_fb) return;
    float B1 = -3.f, B2 = -3.f; int I1 = 0;
    #pragma unroll
    for (int s = 0; s < NSPLIT; s++) {
        size_t o = (size_t)s * NPA + row;
        float vb1 = g_b1[o], vb2 = g_b2[o];
        int vi1 = g_i1[o];
        if (vb1 > B1 || (vb1 == B1 && vi1 < I1)) {
            B2 = fmaxf(B1, vb2); B1 = vb1; I1 = vi1;
        } else {
            B2 = fmaxf(B2, vb1);
        }
    }
    g_idx[row] = I1;
    if (B1 - B2 < MARGIN) {
        int p = atomicAdd(&g_flagCnt, 1);
        if (p < CAP) g_flagRows[p] = row;
    }
}

// ---------------------------------------------------------------------------
// Phase 4a: exact fp32 partial rescan. Block = (flagged row, 1/8 col segment),
// 2-column ILP with float4 loads -> wide MLP instead of a serial load chain.
// ---------------------------------------------------------------------------
__global__ void __launch_bounds__(256) fallback_part_kernel(int n_tw) {
    __shared__ float4 frow4[16];
    __shared__ float sv[256];
    __shared__ int   si[256];
    const int cnt = min(g_flagCnt, CAP);
    const int npairs = cnt * 8;
    const int nseg = (n_tw + 7) >> 3;

    for (int p = blockIdx.x; p < npairs; p += gridDim.x) {
        const int row = g_flagRows[p >> 3];
        const int cs = p & 7;
        const int lo = cs * nseg;
        const int hi = min(lo + nseg, n_tw);

        if (threadIdx.x < 16)
            frow4[threadIdx.x] =
                reinterpret_cast<const float4*>(g_fbn + (size_t)row * D)[threadIdx.x];
        __syncthreads();

        float best = -3.f; int bi = 0;
        for (int c = lo + threadIdx.x * 2; c < hi; c += 512) {
            const bool has1 = (c + 1 < hi);
            const float4* r0 = reinterpret_cast<const float4*>(g_twn + (size_t)c * D);
            const float4* r1 = reinterpret_cast<const float4*>(
                g_twn + (size_t)(has1 ? c + 1 : c) * D);
            float s0 = 0.f, s1 = 0.f;
            #pragma unroll
            for (int kk = 0; kk < 16; kk++) {
                float4 f = frow4[kk];
                float4 a = r0[kk];
                float4 b = r1[kk];
                s0 = fmaf(f.x, a.x, s0); s0 = fmaf(f.y, a.y, s0);
                s0 = fmaf(f.z, a.z, s0); s0 = fmaf(f.w, a.w, s0);
                s1 = fmaf(f.x, b.x, s1); s1 = fmaf(f.y, b.y, s1);
                s1 = fmaf(f.z, b.z, s1); s1 = fmaf(f.w, b.w, s1);
            }
            if (s0 > best) { best = s0; bi = c; }
            if (has1 && s1 > best) { best = s1; bi = c + 1; }
        }
        sv[threadIdx.x] = best; si[threadIdx.x] = bi;
        __syncthreads();
        for (int s = 128; s; s >>= 1) {
            if (threadIdx.x < s) {
                float v = sv[threadIdx.x + s]; int ix = si[threadIdx.x + s];
                if (v > sv[threadIdx.x] ||
                    (v == sv[threadIdx.x] && ix < si[threadIdx.x])) {
                    sv[threadIdx.x] = v; si[threadIdx.x] = ix;
                }
            }
            __syncthreads();
        }
        if (threadIdx.x == 0) { g_pb1[p] = sv[0]; g_pi1[p] = si[0]; }
        __syncthreads();   // frow4/sv reuse on next grid-stride pair
    }
}

// Phase 4b: merge the 8 segment partials per flagged row
__global__ void __launch_bounds__(256) fallback_fin_kernel() {
    int cnt = min(g_flagCnt, CAP);
    int f = blockIdx.x * 256 + threadIdx.x;
    if (f >= cnt) return;
    int row = g_flagRows[f];
    float B = -4.f; int I = 0;
    #pragma unroll
    for (int s = 0; s < 8; s++) {
        float v = g_pb1[f * 8 + s];
        int ix = g_pi1[f * 8 + s];
        if (v > B || (v == B && ix < I)) { B = v; I = ix; }
    }
    g_idx[row] = I;
}

// ---------------------------------------------------------------------------
// Phase 5: head MLPs
// ---------------------------------------------------------------------------
__global__ void __launch_bounds__(256) head_kernel(
    const float* __restrict__ fb, const float* __restrict__ tw,
    const float* __restrict__ Wa1, const float* __restrict__ ba1,
    const float* __restrict__ Wa2, const float* __restrict__ ba2,
    const float* __restrict__ Wo1, const float* __restrict__ bo1,
    const float* __restrict__ Wo2, const float* __restrict__ bo2,
    float* __restrict__ out, int n_fb) {
    __shared__ float concat[8][128];
    __shared__ float wbuf[8][64];

    int w = threadIdx.x >> 5, lane = threadIdx.x & 31;
    int row = blockIdx.x * 8 + w;
    if (row >= n_fb) return;

    int bi = g_idx[row];

    float f0 = fb[(size_t)row * D + lane];
    float f1 = fb[(size_t)row * D + 32 + lane];
    float t0 = tw[(size_t)bi * D + lane];
    float t1 = tw[(size_t)bi * D + 32 + lane];
    concat[w][lane]      = f0;
    concat[w][32 + lane] = f1;
    concat[w][64 + lane] = t0;
    concat[w][96 + lane] = t1;
    __syncwarp();

    float h0 = ba1[lane], h1 = ba1[32 + lane];
    #pragma unroll 8
    for (int k = 0; k < 128; k++) {
        float cv = concat[w][k];
        h0 = fmaf(cv, Wa1[k * 64 + lane], h0);
        h1 = fmaf(cv, Wa1[k * 64 + 32 + lane], h1);
    }
    h0 = fmaxf(h0, 0.0f);
    h1 = fmaxf(h1, 0.0f);

    float p0 = h0 * Wa2[lane * 2 + 0] + h1 * Wa2[(32 + lane) * 2 + 0];
    float p1 = h0 * Wa2[lane * 2 + 1] + h1 * Wa2[(32 + lane) * 2 + 1];
    #pragma unroll
    for (int off = 16; off; off >>= 1) {
        p0 += __shfl_xor_sync(0xffffffffu, p0, off);
        p1 += __shfl_xor_sync(0xffffffffu, p1, off);
    }
    p0 += ba2[0]; p1 += ba2[1];
    float mx = fmaxf(p0, p1);
    float e0 = expf(p0 - mx), e1 = expf(p1 - mx);
    float inv = 1.0f / (e0 + e1);
    float a0 = e0 * inv, a1 = e1 * inv;

    wbuf[w][lane]      = a0 * f0 + a1 * t0;
    wbuf[w][32 + lane] = a0 * f1 + a1 * t1;
    __syncwarp();

    float gg = bo1[lane];
    #pragma unroll 8
    for (int d = 0; d < 64; d++)
        gg = fmaf(wbuf[w][d], Wo1[d * 32 + lane], gg);
    gg = fmaxf(gg, 0.0f);

    float o = gg * Wo2[lane];
    #pragma unroll
    for (int off = 16; off; off >>= 1) o += __shfl_xor_sync(0xffffffffu, o, off);

    if (lane == 0) out[row] = 1.0f / (1.0f + expf(-(o + bo2[0])));
}

// ---------------------------------------------------------------------------
extern "C" void kernel_launch(void* const* d_in, const int* in_sizes, int n_in,
                              void* d_out, int out_size) {
    const float* fb  = (const float*)d_in[0];
    const float* tw  = (const float*)d_in[1];
    const float* Wa1 = (const float*)d_in[2];
    const float* ba1 = (const float*)d_in[3];
    const float* Wa2 = (const float*)d_in[4];
    const float* ba2 = (const float*)d_in[5];
    const float* Wo1 = (const float*)d_in[6];
    const float* bo1 = (const float*)d_in[7];
    const float* Wo2 = (const float*)d_in[8];
    const float* bo2 = (const float*)d_in[9];
    float* out = (float*)d_out;

    int n_fb = in_sizes[0] / D;
    int n_tw = in_sizes[1] / D;

    static int smem_set = 0;
    if (!smem_set) {
        cudaFuncSetAttribute(gemm_tc_kernel,
                             cudaFuncAttributeMaxDynamicSharedMemorySize, SMEM_ALLOC);
        smem_set = 1;
    }

    prep_kernel<<<NPB / 8, 256>>>(fb, tw, n_fb, n_tw);

    dim3 grid((n_fb + 127) / 128, NSPLIT);
    gemm_tc_kernel<<<grid, 512, SMEM_ALLOC>>>(n_fb, n_tw);

    merge_kernel<<<(n_fb + 255) / 256, 256>>>(n_fb);
    fallback_part_kernel<<<1024, 256>>>(n_tw);
    fallback_fin_kernel<<<(CAP + 255) / 256, 256>>>();

    head_kernel<<<(n_fb + 7) / 8, 256>>>(fb, tw, Wa1, ba1, Wa2, ba2,
                                         Wo1, bo1, Wo2, bo2, out, n_fb);
}

// round 6
// speedup vs baseline: 2.0375x; 1.0458x over previous
#include <cuda_runtime.h>
#include <cuda_bf16.h>
#include <math.h>
#include <stdint.h>

#define D 64
#define NPA 20096            // padded fb rows (157*128)
#define NPB 20224            // padded tw rows (158*128)
#define NRB 157              // fb row blocks
#define NTB 158              // tw tiles
#define NSPLIT 8
#define CAP 2048
#define NSEG 32
#define MARGIN 2e-5f

// ---------------- device scratch ----------------
// Swizzled bf16 tiles: per 128-row block, 32KB = [hi 16KB | lo 16KB],
// row r = 128 bytes, 16B chunk c stored at position (c ^ (r&7)).
__device__ char g_fbS[NRB * 32768];
__device__ char g_twS[NTB * 32768];
__device__ float g_fbn[NPA * D];
__device__ float g_twn[NPB * D];
__device__ float g_b1[NSPLIT * NPA];
__device__ float g_b2[NSPLIT * NPA];
__device__ int   g_i1[NSPLIT * NPA];
__device__ int   g_idx[NPA];
__device__ int   g_flagCnt;
__device__ int   g_flagRows[CAP];
__device__ float g_pb1[CAP * NSEG];
__device__ int   g_pi1[CAP * NSEG];

// ---------------- PTX helpers ----------------
__device__ __forceinline__ uint32_t saddr(const void* p) {
    return (uint32_t)__cvta_generic_to_shared(p);
}
__device__ __forceinline__ void ldm_x4(uint32_t* r, uint32_t addr) {
    asm volatile("ldmatrix.sync.aligned.m8n8.x4.shared.b16 {%0,%1,%2,%3}, [%4];"
                 : "=r"(r[0]), "=r"(r[1]), "=r"(r[2]), "=r"(r[3]) : "r"(addr));
}
__device__ __forceinline__ void mma_bf16(float* d, const uint32_t* a,
                                         uint32_t b0, uint32_t b1) {
    asm volatile(
        "mma.sync.aligned.m16n8k16.row.col.f32.bf16.bf16.f32 "
        "{%0,%1,%2,%3}, {%4,%5,%6,%7}, {%8,%9}, {%0,%1,%2,%3};"
        : "+f"(d[0]), "+f"(d[1]), "+f"(d[2]), "+f"(d[3])
        : "r"(a[0]), "r"(a[1]), "r"(a[2]), "r"(a[3]), "r"(b0), "r"(b1));
}

#define MBARRIER_INIT(a, cnt) \
    asm volatile("mbarrier.init.shared.b64 [%0], %1;" :: "r"(a), "r"(cnt) : "memory")
#define MBARRIER_INVAL(a) \
    asm volatile("mbarrier.inval.shared.b64 [%0];" :: "r"(a) : "memory")
#define EXPECT_TX(mbar, bytes) \
    asm volatile("mbarrier.arrive.expect_tx.shared.b64 _, [%0], %1;" \
                 :: "r"(mbar), "r"(bytes) : "memory")
#define BULK_G2S(dst, src, bytes, mbar) \
    asm volatile("cp.async.bulk.shared::cluster.global.mbarrier::complete_tx::bytes " \
                 "[%0], [%1], %2, [%3];" \
                 :: "r"(dst), "l"(src), "r"(bytes), "r"(mbar) : "memory")
#define FENCE_ASYNC() asm volatile("fence.proxy.async;" ::: "memory")

#define MBARRIER_WAIT_PARITY(mbar_smem_addr, phase_parity) do { \
    uint32_t _mbar = (uint32_t)(mbar_smem_addr); \
    uint32_t _parity = (uint32_t)(phase_parity); \
    uint32_t _done; \
    asm volatile( \
        "{\n\t.reg .pred p;\n\t" \
        "mbarrier.try_wait.parity.acquire.cta.shared::cta.b64 p, [%1], %2;\n\t" \
        "selp.b32 %0, 1, 0, p;\n\t}" \
        : "=r"(_done) : "r"(_mbar), "r"(_parity) : "memory"); \
    if (!_done) { \
        asm volatile( \
            "{\n\t.reg .pred P1;\n\t" \
            "WAIT_LOOP_%=:\n\t" \
            "mbarrier.try_wait.parity.acquire.cta.shared::cta.b64 P1, [%0], %1, 0x989680;\n\t" \
            "@P1 bra.uni WAIT_DONE_%=;\n\t" \
            "bra.uni WAIT_LOOP_%=;\n\t" \
            "WAIT_DONE_%=:\n\t}" \
            :: "r"(_mbar), "r"(_parity) : "memory"); \
    } \
} while (0)

// SMEM layout (relative to 1KB-aligned base)
#define MB_A  0
#define MB_B(i) (8 + (i) * 8)
#define SA    1024                       // A: 32KB (hi 16KB | lo 16KB)
#define SB(i) (SA + 32768 + (i) * 32768) // 4 B buffers, 32KB each
#define SMEM_ALLOC (SB(3) + 32768 + 1024)

// ---------------------------------------------------------------------------
// Phase 1: normalize + hi/lo split into SWIZZLED tile layout (+ zero-pad).
// ---------------------------------------------------------------------------
__device__ __forceinline__ void prep_row(const float* __restrict__ in, int n, int row,
                                         int lane, float* __restrict__ nf,
                                         char* __restrict__ sw) {
    int rr = row & 127;
    char* base = sw + (size_t)(row >> 7) * 32768;
    int chunk = (lane >> 2) ^ (rr & 7);
    int off = rr * 128 + (chunk << 4) + (lane & 3) * 4;
    if (row < n) {
        float2 v = reinterpret_cast<const float2*>(in + (size_t)row * D)[lane];
        float ss = v.x * v.x + v.y * v.y;
        #pragma unroll
        for (int o = 16; o; o >>= 1) ss += __shfl_xor_sync(0xffffffffu, ss, o);
        float scale = 1.0f / fmaxf(sqrtf(ss), 1e-8f);
        float a = v.x * scale, b = v.y * scale;
        reinterpret_cast<float2*>(nf + (size_t)row * D)[lane] = make_float2(a, b);
        __nv_bfloat16 ah = __float2bfloat16(a), bh = __float2bfloat16(b);
        __nv_bfloat16 al = __float2bfloat16(a - __bfloat162float(ah));
        __nv_bfloat16 bl = __float2bfloat16(b - __bfloat162float(bh));
        *(__nv_bfloat162*)(base + off)         = __nv_bfloat162(ah, bh);
        *(__nv_bfloat162*)(base + 16384 + off) = __nv_bfloat162(al, bl);
    } else {
        reinterpret_cast<float2*>(nf + (size_t)row * D)[lane] = make_float2(0.f, 0.f);
        __nv_bfloat162 z(__float2bfloat16(0.f), __float2bfloat16(0.f));
        *(__nv_bfloat162*)(base + off)         = z;
        *(__nv_bfloat162*)(base + 16384 + off) = z;
    }
}

__global__ void __launch_bounds__(256) prep_kernel(const float* __restrict__ fb,
                                                   const float* __restrict__ tw,
                                                   int n_fb, int n_tw) {
    if (blockIdx.x == 0 && threadIdx.x == 0) g_flagCnt = 0;
    int w = threadIdx.x >> 5, lane = threadIdx.x & 31;
    int row = blockIdx.x * 8 + w;
    if (row < NPA) prep_row(fb, n_fb, row, lane, g_fbn, g_fbS);
    if (row < NPB) prep_row(tw, n_tw, row, lane, g_twn, g_twS);
}

// ---------------------------------------------------------------------------
// Phase 2: mma.sync bf16 3-term GEMM + fused in-register top-2.
// 512 threads, BM=BN=128, K=64 resident. 4-deep B pipeline via cp.async.bulk;
// A-hi fragments register-resident across the whole tile loop.
// ---------------------------------------------------------------------------
__global__ void __launch_bounds__(512, 1) gemm_tc_kernel(int n_fb, int n_tw) {
    extern __shared__ __align__(128) char smraw[];
    uint32_t sb = (saddr(smraw) + 1023u) & ~1023u;
    char* sbase = smraw + (sb - saddr(smraw));

    const int tid = threadIdx.x;
    const int warp = tid >> 5, lane = tid & 31;
    const int wm = warp >> 2, wn = warp & 3;
    const int g = lane >> 2, tc = lane & 3;
    const int row0 = blockIdx.x * 128;
    const int split = blockIdx.y;

    const int nT = (n_tw + 127) >> 7;
    const int per = (nT + NSPLIT - 1) / NSPLIT;
    const int t0 = split * per;
    const int T = min(t0 + per, nT) - t0;

    if (tid == 0) {
        MBARRIER_INIT(sb + MB_A, 1);
        #pragma unroll
        for (int j = 0; j < 4; j++) MBARRIER_INIT(sb + MB_B(j), 1);
    }
    __syncthreads();
    if (tid == 0) {
        FENCE_ASYNC();
        EXPECT_TX(sb + MB_A, 32768u);
        BULK_G2S(sb + SA, g_fbS + (size_t)blockIdx.x * 32768, 32768u, sb + MB_A);
        #pragma unroll
        for (int j = 0; j < 4; j++) {
            if (j < T) {
                EXPECT_TX(sb + MB_B(j), 32768u);
                BULK_G2S(sb + SB(j), g_twS + (size_t)(t0 + j) * 32768, 32768u,
                         sb + MB_B(j));
            }
        }
    }

    float b1[4] = {-2.f, -2.f, -2.f, -2.f};
    float b2[4] = {-2.f, -2.f, -2.f, -2.f};
    int   i1[4] = {0, 0, 0, 0};

    const int rA = wm * 32 + (lane & 15);
    const int rB = wn * 32 + (lane & 15);
    const int swA = rA & 7, swB = rB & 7;
    const uint32_t aBase = sb + SA + rA * 128;
    const int cHalf = (lane >> 4);

    // A-hi fragments for all 4 k-steps: resident for the whole tile loop
    MBARRIER_WAIT_PARITY(sb + MB_A, 0);
    uint32_t ahR[4][2][4];
    #pragma unroll
    for (int ks = 0; ks < 4; ks++) {
        const uint32_t aOff = (uint32_t)((((ks * 2 + cHalf)) ^ swA) << 4);
        #pragma unroll
        for (int x = 0; x < 2; x++)
            ldm_x4(ahR[ks][x], aBase + x * 2048 + aOff);
    }

    for (int i = 0; i < T; i++) {
        const int buf = i & 3;
        const uint32_t SBx = sb + SB(buf);
        const uint32_t mb = sb + MB_B(buf);
        MBARRIER_WAIT_PARITY(mb, (i >> 2) & 1);

        const uint32_t bBase = SBx + rB * 128;

        float acc[2][4][4];
        #pragma unroll
        for (int x = 0; x < 2; x++)
            #pragma unroll
            for (int t = 0; t < 4; t++)
                #pragma unroll
                for (int q = 0; q < 4; q++) acc[x][t][q] = 0.f;

        #pragma unroll
        for (int ks = 0; ks < 4; ks++) {
            const int cc = ks * 2 + cHalf;
            const uint32_t aOff = (uint32_t)((cc ^ swA) << 4);
            const uint32_t bOff = (uint32_t)((cc ^ swB) << 4);
            uint32_t al[2][4], bh[2][4], bl[2][4];
            #pragma unroll
            for (int x = 0; x < 2; x++)
                ldm_x4(al[x], aBase + x * 2048 + 16384 + aOff);
            #pragma unroll
            for (int j = 0; j < 2; j++) {
                ldm_x4(bh[j], bBase + j * 2048 + bOff);
                ldm_x4(bl[j], bBase + j * 2048 + 16384 + bOff);
            }
            #pragma unroll
            for (int x = 0; x < 2; x++)
                #pragma unroll
                for (int t = 0; t < 4; t++) {
                    int j = t >> 1, s = t & 1;
                    mma_bf16(acc[x][t], ahR[ks][x], bh[j][s], bh[j][s + 2]);
                    mma_bf16(acc[x][t], ahR[ks][x], bl[j][s], bl[j][s + 2]);
                    mma_bf16(acc[x][t], al[x], bh[j][s], bh[j][s + 2]);
                }
        }

        // all smem reads of this buffer done -> refill for tile i+4 while the
        // register-only epilogue runs
        __syncthreads();
        if (tid == 0 && i + 4 < T) {
            EXPECT_TX(mb, 32768u);
            BULK_G2S(SBx, g_twS + (size_t)(t0 + i + 4) * 32768, 32768u, mb);
        }

        const int col0 = (t0 + i) << 7;
        const bool full = (col0 + 128 <= n_tw);
        const int nb = col0 + wn * 32 + 2 * tc;
        #pragma unroll
        for (int x = 0; x < 2; x++)
            #pragma unroll
            for (int t = 0; t < 4; t++) {
                int n0 = nb + t * 8;
                #pragma unroll
                for (int q = 0; q < 4; q++) {
                    int lr = x * 2 + (q >> 1);
                    int n = n0 + (q & 1);
                    float v = acc[x][t][q];
                    if (full || n < n_tw) {
                        if (v > b1[lr]) { b2[lr] = b1[lr]; b1[lr] = v; i1[lr] = n; }
                        else if (v > b2[lr]) b2[lr] = v;
                    }
                }
            }
    }

    // cross-lane (tc) merge
    #pragma unroll
    for (int lr = 0; lr < 4; lr++) {
        #pragma unroll
        for (int off = 1; off <= 2; off <<= 1) {
            float ob1 = __shfl_xor_sync(0xffffffffu, b1[lr], off);
            float ob2 = __shfl_xor_sync(0xffffffffu, b2[lr], off);
            int   oi1 = __shfl_xor_sync(0xffffffffu, i1[lr], off);
            if (ob1 > b1[lr] || (ob1 == b1[lr] && oi1 < i1[lr])) {
                b2[lr] = fmaxf(b1[lr], ob2); b1[lr] = ob1; i1[lr] = oi1;
            } else {
                b2[lr] = fmaxf(b2[lr], ob1);
            }
        }
    }

    // cross-warp merge via smem (overlay on A region; A fully consumed)
    __syncthreads();
    float* redB1 = (float*)(sbase + SA);
    float* redB2 = redB1 + 512;
    int*   redI1 = (int*)(redB2 + 512);
    if (tc == 0) {
        #pragma unroll
        for (int lr = 0; lr < 4; lr++) {
            int row = wm * 32 + (lr >> 1) * 16 + g + (lr & 1) * 8;
            redB1[row * 4 + wn] = b1[lr];
            redB2[row * 4 + wn] = b2[lr];
            redI1[row * 4 + wn] = i1[lr];
        }
    }
    __syncthreads();
    if (tid < 128) {
        float B1 = -3.f, B2 = -3.f; int I1 = 0;
        #pragma unroll
        for (int w = 0; w < 4; w++) {
            float vb1 = redB1[tid * 4 + w], vb2 = redB2[tid * 4 + w];
            int vi1 = redI1[tid * 4 + w];
            if (vb1 > B1 || (vb1 == B1 && vi1 < I1)) {
                B2 = fmaxf(B1, vb2); B1 = vb1; I1 = vi1;
            } else {
                B2 = fmaxf(B2, vb1);
            }
        }
        size_t o = (size_t)split * NPA + row0 + tid;
        g_b1[o] = B1; g_b2[o] = B2; g_i1[o] = I1;
    }
    __syncthreads();
    if (tid == 0) {
        MBARRIER_INVAL(sb + MB_A);
        #pragma unroll
        for (int j = 0; j < 4; j++) MBARRIER_INVAL(sb + MB_B(j));
    }
}

// ---------------------------------------------------------------------------
// Phase 3: merge splits -> final idx + flag ambiguous rows
// ---------------------------------------------------------------------------
__global__ void __launch_bounds__(256) merge_kernel(int n_fb) {
    int row = blockIdx.x * 256 + threadIdx.x;
    if (row >= n_fb) return;
    float B1 = -3.f, B2 = -3.f; int I1 = 0;
    #pragma unroll
    for (int s = 0; s < NSPLIT; s++) {
        size_t o = (size_t)s * NPA + row;
        float vb1 = g_b1[o], vb2 = g_b2[o];
        int vi1 = g_i1[o];
        if (vb1 > B1 || (vb1 == B1 && vi1 < I1)) {
            B2 = fmaxf(B1, vb2); B1 = vb1; I1 = vi1;
        } else {
            B2 = fmaxf(B2, vb1);
        }
    }
    g_idx[row] = I1;
    if (B1 - B2 < MARGIN) {
        int p = atomicAdd(&g_flagCnt, 1);
        if (p < CAP) g_flagRows[p] = row;
    }
}

// ---------------------------------------------------------------------------
// Phase 4a: exact fp32 partial rescan. Block = (flagged row, 1/32 col segment).
// ---------------------------------------------------------------------------
__global__ void __launch_bounds__(256) fallback_part_kernel(int n_tw) {
    __shared__ float4 frow4[16];
    __shared__ float sv[256];
    __shared__ int   si[256];
    const int cnt = min(g_flagCnt, CAP);
    const int npairs = cnt * NSEG;
    const int nseg = (n_tw + NSEG - 1) / NSEG;

    for (int p = blockIdx.x; p < npairs; p += gridDim.x) {
        const int row = g_flagRows[p / NSEG];
        const int cs = p % NSEG;
        const int lo = cs * nseg;
        const int hi = min(lo + nseg, n_tw);

        if (threadIdx.x < 16)
            frow4[threadIdx.x] =
                reinterpret_cast<const float4*>(g_fbn + (size_t)row * D)[threadIdx.x];
        __syncthreads();

        float best = -3.f; int bi = 0;
        for (int c = lo + threadIdx.x * 2; c < hi; c += 512) {
            const bool has1 = (c + 1 < hi);
            const float4* r0 = reinterpret_cast<const float4*>(g_twn + (size_t)c * D);
            const float4* r1 = reinterpret_cast<const float4*>(
                g_twn + (size_t)(has1 ? c + 1 : c) * D);
            float s0 = 0.f, s1 = 0.f;
            #pragma unroll
            for (int kk = 0; kk < 16; kk++) {
                float4 f = frow4[kk];
                float4 a = r0[kk];
                float4 b = r1[kk];
                s0 = fmaf(f.x, a.x, s0); s0 = fmaf(f.y, a.y, s0);
                s0 = fmaf(f.z, a.z, s0); s0 = fmaf(f.w, a.w, s0);
                s1 = fmaf(f.x, b.x, s1); s1 = fmaf(f.y, b.y, s1);
                s1 = fmaf(f.z, b.z, s1); s1 = fmaf(f.w, b.w, s1);
            }
            if (s0 > best) { best = s0; bi = c; }
            if (has1 && s1 > best) { best = s1; bi = c + 1; }
        }
        sv[threadIdx.x] = best; si[threadIdx.x] = bi;
        __syncthreads();
        for (int s = 128; s; s >>= 1) {
            if (threadIdx.x < s) {
                float v = sv[threadIdx.x + s]; int ix = si[threadIdx.x + s];
                if (v > sv[threadIdx.x] ||
                    (v == sv[threadIdx.x] && ix < si[threadIdx.x])) {
                    sv[threadIdx.x] = v; si[threadIdx.x] = ix;
                }
            }
            __syncthreads();
        }
        if (threadIdx.x == 0) { g_pb1[p] = sv[0]; g_pi1[p] = si[0]; }
        __syncthreads();
    }
}

// Phase 4b: merge the NSEG segment partials per flagged row
__global__ void __launch_bounds__(256) fallback_fin_kernel() {
    int cnt = min(g_flagCnt, CAP);
    int f = blockIdx.x * 256 + threadIdx.x;
    if (f >= cnt) return;
    int row = g_flagRows[f];
    float B = -4.f; int I = 0;
    #pragma unroll 8
    for (int s = 0; s < NSEG; s++) {
        float v = g_pb1[f * NSEG + s];
        int ix = g_pi1[f * NSEG + s];
        if (v > B || (v == B && ix < I)) { B = v; I = ix; }
    }
    g_idx[row] = I;
}

// ---------------------------------------------------------------------------
// Phase 5: head MLPs. Warp handles 4 rows -> weight reads amortized 4x.
// ---------------------------------------------------------------------------
__global__ void __launch_bounds__(256) head_kernel(
    const float* __restrict__ fb, const float* __restrict__ tw,
    const float* __restrict__ Wa1, const float* __restrict__ ba1,
    const float* __restrict__ Wa2, const float* __restrict__ ba2,
    const float* __restrict__ Wo1, const float* __restrict__ bo1,
    const float* __restrict__ Wo2, const float* __restrict__ bo2,
    float* __restrict__ out, int n_fb) {
    __shared__ float concat[32][128];
    __shared__ float wbuf[32][64];

    const int w = threadIdx.x >> 5, lane = threadIdx.x & 31;
    const int rbase = blockIdx.x * 32 + w * 4;

    float f0[4], f1[4], tv0[4], tv1[4];
    #pragma unroll
    for (int rr = 0; rr < 4; rr++) {
        int row = rbase + rr;
        if (row < n_fb) {
            int bi = g_idx[row];
            f0[rr] = fb[(size_t)row * D + lane];
            f1[rr] = fb[(size_t)row * D + 32 + lane];
            tv0[rr] = tw[(size_t)bi * D + lane];
            tv1[rr] = tw[(size_t)bi * D + 32 + lane];
            concat[w * 4 + rr][lane]      = f0[rr];
            concat[w * 4 + rr][32 + lane] = f1[rr];
            concat[w * 4 + rr][64 + lane] = tv0[rr];
            concat[w * 4 + rr][96 + lane] = tv1[rr];
        }
    }
    __syncwarp();

    const float bz0 = ba1[lane], bz1 = ba1[32 + lane];
    float h0[4], h1[4];
    #pragma unroll
    for (int rr = 0; rr < 4; rr++) { h0[rr] = bz0; h1[rr] = bz1; }

    #pragma unroll 4
    for (int k = 0; k < 128; k++) {
        float w0 = Wa1[k * 64 + lane];
        float w1 = Wa1[k * 64 + 32 + lane];
        #pragma unroll
        for (int rr = 0; rr < 4; rr++) {
            float cv = concat[w * 4 + rr][k];
            h0[rr] = fmaf(cv, w0, h0[rr]);
            h1[rr] = fmaf(cv, w1, h1[rr]);
        }
    }

    const float wa20 = Wa2[lane * 2 + 0], wa21 = Wa2[lane * 2 + 1];
    const float wa30 = Wa2[(32 + lane) * 2 + 0], wa31 = Wa2[(32 + lane) * 2 + 1];
    #pragma unroll
    for (int rr = 0; rr < 4; rr++) {
        float a = fmaxf(h0[rr], 0.f), b = fmaxf(h1[rr], 0.f);
        float p0 = a * wa20 + b * wa30;
        float p1 = a * wa21 + b * wa31;
        #pragma unroll
        for (int off = 16; off; off >>= 1) {
            p0 += __shfl_xor_sync(0xffffffffu, p0, off);
            p1 += __shfl_xor_sync(0xffffffffu, p1, off);
        }
        p0 += ba2[0]; p1 += ba2[1];
        float mx = fmaxf(p0, p1);
        float e0 = expf(p0 - mx), e1 = expf(p1 - mx);
        float inv = 1.0f / (e0 + e1);
        float a0 = e0 * inv, a1 = e1 * inv;
        wbuf[w * 4 + rr][lane]      = a0 * f0[rr] + a1 * tv0[rr];
        wbuf[w * 4 + rr][32 + lane] = a0 * f1[rr] + a1 * tv1[rr];
    }
    __syncwarp();

    const float bo = bo1[lane];
    float gg[4];
    #pragma unroll
    for (int rr = 0; rr < 4; rr++) gg[rr] = bo;
    #pragma unroll 4
    for (int d = 0; d < 64; d++) {
        float wv = Wo1[d * 32 + lane];
        #pragma unroll
        for (int rr = 0; rr < 4; rr++)
            gg[rr] = fmaf(wbuf[w * 4 + rr][d], wv, gg[rr]);
    }
    const float wo2 = Wo2[lane];
    #pragma unroll
    for (int rr = 0; rr < 4; rr++) {
        float o = fmaxf(gg[rr], 0.f) * wo2;
        #pragma unroll
        for (int off = 16; off; off >>= 1) o += __shfl_xor_sync(0xffffffffu, o, off);
        int row = rbase + rr;
        if (lane == 0 && row < n_fb)
            out[row] = 1.0f / (1.0f + expf(-(o + bo2[0])));
    }
}

// ---------------------------------------------------------------------------
extern "C" void kernel_launch(void* const* d_in, const int* in_sizes, int n_in,
                              void* d_out, int out_size) {
    const float* fb  = (const float*)d_in[0];
    const float* tw  = (const float*)d_in[1];
    const float* Wa1 = (const float*)d_in[2];
    const float* ba1 = (const float*)d_in[3];
    const float* Wa2 = (const float*)d_in[4];
    const float* ba2 = (const float*)d_in[5];
    const float* Wo1 = (const float*)d_in[6];
    const float* bo1 = (const float*)d_in[7];
    const float* Wo2 = (const float*)d_in[8];
    const float* bo2 = (const float*)d_in[9];
    float* out = (float*)d_out;

    int n_fb = in_sizes[0] / D;
    int n_tw = in_sizes[1] / D;

    static int smem_set = 0;
    if (!smem_set) {
        cudaFuncSetAttribute(gemm_tc_kernel,
                             cudaFuncAttributeMaxDynamicSharedMemorySize, SMEM_ALLOC);
        smem_set = 1;
    }

    prep_kernel<<<NPB / 8, 256>>>(fb, tw, n_fb, n_tw);

    dim3 grid((n_fb + 127) / 128, NSPLIT);
    gemm_tc_kernel<<<grid, 512, SMEM_ALLOC>>>(n_fb, n_tw);

    merge_kernel<<<(n_fb + 255) / 256, 256>>>(n_fb);
    fallback_part_kernel<<<2048, 256>>>(n_tw);
    fallback_fin_kernel<<<(CAP + 255) / 256, 256>>>();

    head_kernel<<<(n_fb + 31) / 32, 256>>>(fb, tw, Wa1, ba1, Wa2, ba2,
                                           Wo1, bo1, Wo2, bo2, out, n_fb);
}